// round 10
// baseline (speedup 1.0000x reference)
#include <cuda_runtime.h>

#define FM 0xffffffffu

__device__ __forceinline__ float artanh_(float x) {
    x = fminf(fmaxf(x, -1.f + 1e-7f), 1.f - 1e-7f);
    return 0.5f * logf((1.f + x) / (1.f - x));
}

__device__ __forceinline__ float wred32(float v) {
#pragma unroll
    for (int o = 16; o; o >>= 1) v += __shfl_xor_sync(FM, v, o);
    return v;
}

__device__ __forceinline__ float gred16(float v) {
#pragma unroll
    for (int o = 8; o; o >>= 1) v += __shfl_xor_sync(FM, v, o);
    return v;
}

enum { X2SELF = 0, X2IV, FSELF, FIV,
       N2AGGE, N2AGGU, DSAE, DIAU,
       N2KG, DSKG, N2UA, N2O1, DO1UA,
       XN2, MXN2, NB2, NRES2, NHB2, DRH, N2O3, N2T, NSC };

// Scratch for raw attention bilinear forms: E_raw[b][s] = self · Wr[b,s] · engh[b,s]
__device__ float g_Escratch[4096 * 16];

// ==================== Kernel A: pure Wr stream ====================
// grid (B, 4), 128 threads. Warp w of s-group sg handles s = sg*4 + w.
// Computes E_raw with RAW vectors (logmap0 scalars factored out into kernel B).
__global__ __launch_bounds__(128)
void wr_stream_kernel(const float* __restrict__ g_self,   // (B,1,64)
                      const float* __restrict__ g_engh,   // (B,1,16,64)
                      const float* __restrict__ g_Wr)     // (B,1,16,64,64)
{
    const int b    = blockIdx.x;
    const int sg   = blockIdx.y;      // 0..3
    const int tid  = threadIdx.x;
    const int lane = tid & 31;
    const int warp = tid >> 5;        // 0..3

    __shared__ float s_self[64];
    __shared__ float s_engh[4][64];

    if (tid < 64) s_self[tid] = g_self[b * 64 + tid];
#pragma unroll
    for (int i = tid; i < 256; i += 128)
        (&s_engh[0][0])[i] = g_engh[(size_t)b * 1024 + sg * 256 + i];
    __syncthreads();

    const int si  = sg * 4 + warp;
    const int l15 = lane & 15;
    const int hi  = lane >> 4;
    const float4 a = *reinterpret_cast<const float4*>(&s_self[4 * l15]);
    // Each iteration: warp reads 2 full rows (512B) of Wr[b,si], coalesced LDG.128.
    const float4* p = reinterpret_cast<const float4*>(g_Wr)
                    + (size_t)b * 16384 + (size_t)si * 1024 + lane;
    float acc = 0.f;
#pragma unroll 8
    for (int i = 0; i < 32; i++) {
        float4 w = __ldcs(p + i * 32);
        acc += s_engh[warp][2 * i + hi] * (w.x * a.x + w.y * a.y + w.z * a.z + w.w * a.w);
    }
    acc = wred32(acc);
    if (lane == 0) g_Escratch[b * 16 + si] = acc;
}

// ==================== Kernel B: epilogue ====================
__global__ __launch_bounds__(256)
void kgagg_epilogue(const float* __restrict__ g_self,   // (B,1,64)
                    const float* __restrict__ g_ungh,   // (B,16,64)
                    const float* __restrict__ g_engh,   // (B,1,16,64)
                    const float* __restrict__ g_item,   // (B,64)
                    const float* __restrict__ g_Wui,    // (64,64)
                    const float* __restrict__ g_linW,   // (64,64)
                    const float* __restrict__ g_linb,   // (64,)
                    float* __restrict__ g_out)          // (B,1,64)
{
    const int b    = blockIdx.x;
    const int tid  = threadIdx.x;
    const int lane = tid & 31;
    const int warp = tid >> 5;
    const float MAXN = 1.f - 0.004f;

    __shared__ float s_self[64], s_iv[64], s_titem[64];
    __shared__ float s_engh[16][64], s_ungh[16][64];
    __shared__ float s_te[16][64], s_tu[16][64];   // s_tu = t_ungh; both reused for sub
    __shared__ float s_y2e[16], s_xye[16], s_y2u[16], s_xyu[16];
    __shared__ float s_fe[16], s_fu[16];
    __shared__ float s_e[16], s_ue[16], s_att[16], s_uatt[16];
    __shared__ float s_sn2e[16], s_sn2u[16], s_ce[16], s_cu[16];
    __shared__ float s_imW[64], s_mx[64];
    __shared__ float s_aggE[64], s_aggU[64], s_kg[64], s_ua[64];
    __shared__ float s_o1[64], s_o2[64], s_res[64], s_hb[64], s_o3[64], s_t[64];
    __shared__ float sc[NSC];

    // ---------------- Phase 0: load small tensors ----------------
    if (tid < 64)            s_self[tid]      = g_self[b * 64 + tid];
    else if (tid < 128)      s_iv[tid - 64]   = g_item[b * 64 + (tid - 64)];
#pragma unroll
    for (int i = tid; i < 1024; i += 256) {
        (&s_engh[0][0])[i] = g_engh[(size_t)b * 1024 + i];
        (&s_ungh[0][0])[i] = g_ungh[(size_t)b * 1024 + i];
    }
    __syncthreads();

    // ---------------- Phase A: per-s norms/dots + self/iv norms ----------------
    {
        int g = tid >> 4, l = tid & 15;
        float pe = 0.f, pxe = 0.f, pu = 0.f, pxu = 0.f;
#pragma unroll
        for (int k = 0; k < 4; k++) {
            int d = l + 16 * k;
            float ev = s_engh[g][d]; pe += ev * ev; pxe += ev * s_self[d];
            float uv = s_ungh[g][d]; pu += uv * uv; pxu += uv * s_iv[d];
        }
        pe = gred16(pe); pxe = gred16(pxe); pu = gred16(pu); pxu = gred16(pxu);
        if (l == 0) { s_y2e[g] = pe; s_xye[g] = pxe; s_y2u[g] = pu; s_xyu[g] = pxu; }

        float v = 0.f;
        if (warp == 0)      { float a = s_self[lane], c = s_self[lane + 32]; v = a * a + c * c; }
        else if (warp == 1) { float a = s_iv[lane],   c = s_iv[lane + 32];   v = a * a + c * c; }
        v = wred32(v);
        if (lane == 0) { if (warp == 0) sc[X2SELF] = v; else if (warp == 1) sc[X2IV] = v; }
    }
    __syncthreads();

    // ---------------- Phase A2: logmap0 scale factors ----------------
    if (tid < 16) {
        float ne = fmaxf(sqrtf(s_y2e[tid]), 1e-15f);
        s_fe[tid] = artanh_(ne) / ne;
    } else if (tid < 32) {
        int s = tid - 16;
        float nu = fmaxf(sqrtf(s_y2u[s]), 1e-15f);
        s_fu[s] = artanh_(nu) / nu;
    } else if (tid == 32) {
        float n = fmaxf(sqrtf(sc[X2SELF]), 1e-15f);
        sc[FSELF] = artanh_(n) / n;
    } else if (tid == 33) {
        float n = fmaxf(sqrtf(sc[X2IV]), 1e-15f);
        sc[FIV] = artanh_(n) / n;
    }
    __syncthreads();

    // ---------------- Phase B: apply logmap0 + pick up streamed logits ----------------
    if (tid < 64)       s_titem[tid] = sc[FIV] * s_iv[tid];
    else if (tid < 80)  {
        int s = tid - 64;
        s_e[s] = sc[FSELF] * s_fe[s] * g_Escratch[b * 16 + s];
    }
#pragma unroll
    for (int i = tid; i < 1024; i += 256) {
        int s = i >> 6;
        (&s_tu[0][0])[i] = s_fu[s] * (&s_ungh[0][0])[i];
    }
    __syncthreads();

    // ---------------- Phase C: imW[r] = sum_d t_item[d] * W_ui[r,d] ----------------
#pragma unroll
    for (int r = warp; r < 64; r += 8) {
        float v = g_Wui[r * 64 + lane] * s_titem[lane]
                + g_Wui[r * 64 + lane + 32] * s_titem[lane + 32];
        v = wred32(v);
        if (lane == 0) s_imW[r] = v;
    }
    __syncthreads();

    // ---------------- Phase D: u_e[s] = dot(imW, t_ungh[s]) ----------------
    {
        int g = tid >> 4, l = tid & 15;
        float p = 0.f;
#pragma unroll
        for (int k = 0; k < 4; k++) { int r = l + 16 * k; p += s_imW[r] * s_tu[g][r]; }
        p = gred16(p);
        if (l == 0) s_ue[g] = p;
    }
    __syncthreads();

    // ---------------- Phase E: softmaxes over s ----------------
    if (warp < 2) {
        const float* src = (warp == 0) ? s_e : s_ue;
        float* dst       = (warp == 0) ? s_att : s_uatt;
        float v = (lane < 16) ? src[lane] : -1e30f;
        float m = v;
#pragma unroll
        for (int o = 16; o; o >>= 1) m = fmaxf(m, __shfl_xor_sync(FM, m, o));
        float ex = (lane < 16) ? expf(v - m) : 0.f;
        float sum = wred32(ex);
        if (lane < 16) dst[lane] = ex / sum;
    }
    __syncthreads();

    // ---------------- Phase F: sub = mobius_add(-p, y) for entity & user ----------------
    {
        float x2s = sc[X2SELF], x2i = sc[X2IV];
#pragma unroll
        for (int i = tid; i < 2048; i += 256) {
            if (i < 1024) {
                int s = i >> 6, d = i & 63;
                float t2 = 2.f * s_xye[s];
                float cx = -(1.f - t2 + s_y2e[s]);
                float cy = 1.f - x2s;
                float den = fmaxf(1.f - t2 + x2s * s_y2e[s], 1e-15f);
                (&s_te[0][0])[i] = (cx * s_self[d] + cy * s_engh[s][d]) / den;
            } else {
                int j = i - 1024, s = j >> 6, d = j & 63;
                float t2 = 2.f * s_xyu[s];
                float cx = -(1.f - t2 + s_y2u[s]);
                float cy = 1.f - x2i;
                float den = fmaxf(1.f - t2 + x2i * s_y2u[s], 1e-15f);
                (&s_tu[0][0])[j] = (cx * s_iv[d] + cy * s_ungh[s][d]) / den;
            }
        }
    }
    __syncthreads();

    // sub norms
    {
        int g = tid >> 4, l = tid & 15;
        float pe = 0.f, pu = 0.f;
#pragma unroll
        for (int k = 0; k < 4; k++) {
            int d = l + 16 * k;
            float v = s_te[g][d]; pe += v * v;
            float u = s_tu[g][d]; pu += u * u;
        }
        pe = gred16(pe); pu = gred16(pu);
        if (l == 0) { s_sn2e[g] = pe; s_sn2u[g] = pu; }
    }
    __syncthreads();

    // att-weighted logmap coefficients
    if (tid < 16) {
        float lam = fmaxf(2.f / (1.f - sc[X2SELF]), 1e-15f);
        float sn  = fmaxf(sqrtf(s_sn2e[tid]), 1e-15f);
        s_ce[tid] = s_att[tid] * (2.f / lam) * artanh_(sn) / sn;
    } else if (tid < 32) {
        int s = tid - 16;
        float lam = fmaxf(2.f / (1.f - sc[X2IV]), 1e-15f);
        float sn  = fmaxf(sqrtf(s_sn2u[s]), 1e-15f);
        s_cu[s] = s_uatt[s] * (2.f / lam) * artanh_(sn) / sn;
    }
    __syncthreads();

    // aggregate over s
    if (tid < 64) {
        float a = 0.f;
#pragma unroll
        for (int s = 0; s < 16; s++) a += s_ce[s] * s_te[s][tid];
        s_aggE[tid] = a;
    } else if (tid < 128) {
        int d = tid - 64;
        float a = 0.f;
#pragma unroll
        for (int s = 0; s < 16; s++) a += s_cu[s] * s_tu[s][d];
        s_aggU[d] = a;
    }
    __syncthreads();

    // R1: norms/dots of aggregates
    {
        float v = 0.f;
        if (warp == 0)      v = s_aggE[lane] * s_aggE[lane] + s_aggE[lane + 32] * s_aggE[lane + 32];
        else if (warp == 1) v = s_aggU[lane] * s_aggU[lane] + s_aggU[lane + 32] * s_aggU[lane + 32];
        else if (warp == 2) v = s_self[lane] * s_aggE[lane] + s_self[lane + 32] * s_aggE[lane + 32];
        else if (warp == 3) v = s_iv[lane]   * s_aggU[lane] + s_iv[lane + 32]   * s_aggU[lane + 32];
        v = wred32(v);
        if (lane == 0) {
            if (warp == 0) sc[N2AGGE] = v; else if (warp == 1) sc[N2AGGU] = v;
            else if (warp == 2) sc[DSAE] = v; else if (warp == 3) sc[DIAU] = v;
        }
    }
    __syncthreads();

    // expmap at base point + mobius_add(base, second)  -> kg, ua
    {
        float x2s = sc[X2SELF], x2i = sc[X2IV];
        if (tid < 64) {
            float un  = fmaxf(sqrtf(sc[N2AGGE]), 1e-15f);
            float lam = fmaxf(2.f / (1.f - x2s), 1e-15f);
            float f   = tanhf(lam * un * 0.5f) / un;
            float xy = f * sc[DSAE], y2 = f * f * sc[N2AGGE];
            float den = fmaxf(1.f + 2.f * xy + x2s * y2, 1e-15f);
            s_kg[tid] = ((1.f + 2.f * xy + y2) * s_self[tid] + (1.f - x2s) * f * s_aggE[tid]) / den;
        } else if (tid < 128) {
            int d = tid - 64;
            float un  = fmaxf(sqrtf(sc[N2AGGU]), 1e-15f);
            float lam = fmaxf(2.f / (1.f - x2i), 1e-15f);
            float f   = tanhf(lam * un * 0.5f) / un;
            float xy = f * sc[DIAU], y2 = f * f * sc[N2AGGU];
            float den = fmaxf(1.f + 2.f * xy + x2i * y2, 1e-15f);
            s_ua[d] = ((1.f + 2.f * xy + y2) * s_iv[d] + (1.f - x2i) * f * s_aggU[d]) / den;
        }
    }
    __syncthreads();

    // R2
    {
        float v = 0.f;
        if (warp == 0)      v = s_kg[lane] * s_kg[lane]   + s_kg[lane + 32] * s_kg[lane + 32];
        else if (warp == 1) v = s_self[lane] * s_kg[lane] + s_self[lane + 32] * s_kg[lane + 32];
        else if (warp == 2) v = s_ua[lane] * s_ua[lane]   + s_ua[lane + 32] * s_ua[lane + 32];
        v = wred32(v);
        if (lane == 0) {
            if (warp == 0) sc[N2KG] = v; else if (warp == 1) sc[DSKG] = v;
            else if (warp == 2) sc[N2UA] = v;
        }
    }
    __syncthreads();

    // o1 = mobius_add(self, kg)
    if (tid < 64) {
        float x2 = sc[X2SELF], y2 = sc[N2KG], xy = sc[DSKG];
        float den = fmaxf(1.f + 2.f * xy + x2 * y2, 1e-15f);
        s_o1[tid] = ((1.f + 2.f * xy + y2) * s_self[tid] + (1.f - x2) * s_kg[tid]) / den;
    }
    __syncthreads();

    // R3
    {
        float v = 0.f;
        if (warp == 0)      v = s_o1[lane] * s_o1[lane] + s_o1[lane + 32] * s_o1[lane + 32];
        else if (warp == 1) v = s_o1[lane] * s_ua[lane] + s_o1[lane + 32] * s_ua[lane + 32];
        v = wred32(v);
        if (lane == 0) { if (warp == 0) sc[N2O1] = v; else if (warp == 1) sc[DO1UA] = v; }
    }
    __syncthreads();

    // o2 = mobius_add(o1, ua)
    if (tid < 64) {
        float x2 = sc[N2O1], y2 = sc[N2UA], xy = sc[DO1UA];
        float den = fmaxf(1.f + 2.f * xy + x2 * y2, 1e-15f);
        s_o2[tid] = ((1.f + 2.f * xy + y2) * s_o1[tid] + (1.f - x2) * s_ua[tid]) / den;
    }
    __syncthreads();

    // mx = lin_W @ o2
#pragma unroll
    for (int r = warp; r < 64; r += 8) {
        float v = g_linW[r * 64 + lane] * s_o2[lane]
                + g_linW[r * 64 + lane + 32] * s_o2[lane + 32];
        v = wred32(v);
        if (lane == 0) s_mx[r] = v;
    }
    __syncthreads();

    // R5
    {
        float v = 0.f;
        if (warp == 0)      { float a = s_mx[lane],    c = s_mx[lane + 32];    v = a * a + c * c; }
        else if (warp == 1) { float a = g_linb[lane],  c = g_linb[lane + 32];  v = a * a + c * c; }
        else if (warp == 2) { float a = s_o2[lane],    c = s_o2[lane + 32];    v = a * a + c * c; }
        v = wred32(v);
        if (lane == 0) {
            if (warp == 0) sc[MXN2] = v; else if (warp == 1) sc[NB2] = v;
            else if (warp == 2) sc[XN2] = v;
        }
    }
    __syncthreads();

    // res = mobius_matvec scale; hb = expmap0(lin_b)
    if (tid < 64) {
        float xn  = fmaxf(sqrtf(sc[XN2]),  1e-15f);
        float mxn = fmaxf(sqrtf(sc[MXN2]), 1e-15f);
        float f = tanhf(mxn / xn * artanh_(xn)) / mxn;
        s_res[tid] = f * s_mx[tid];
    } else if (tid < 128) {
        int d = tid - 64;
        float nb = fmaxf(sqrtf(sc[NB2]), 1e-15f);
        float f = tanhf(nb) / nb;
        s_hb[d] = f * g_linb[d];
    }
    __syncthreads();

    // R6
    {
        float v = 0.f;
        if (warp == 0)      v = s_res[lane] * s_res[lane] + s_res[lane + 32] * s_res[lane + 32];
        else if (warp == 1) v = s_hb[lane]  * s_hb[lane]  + s_hb[lane + 32]  * s_hb[lane + 32];
        else if (warp == 2) v = s_res[lane] * s_hb[lane]  + s_res[lane + 32] * s_hb[lane + 32];
        v = wred32(v);
        if (lane == 0) {
            if (warp == 0) sc[NRES2] = v; else if (warp == 1) sc[NHB2] = v;
            else if (warp == 2) sc[DRH] = v;
        }
    }
    __syncthreads();

    // o3 = mobius_add(proj(res), proj(hb))
    if (tid < 64) {
        float nr = fmaxf(sqrtf(sc[NRES2]), 1e-15f);
        float pr = (nr > MAXN) ? MAXN / nr : 1.f;
        float nh = fmaxf(sqrtf(sc[NHB2]), 1e-15f);
        float ph = (nh > MAXN) ? MAXN / nh : 1.f;
        float x2 = pr * pr * sc[NRES2];
        float y2 = ph * ph * sc[NHB2];
        float xy = pr * ph * sc[DRH];
        float den = fmaxf(1.f + 2.f * xy + x2 * y2, 1e-15f);
        s_o3[tid] = ((1.f + 2.f * xy + y2) * pr * s_res[tid] + (1.f - x2) * ph * s_hb[tid]) / den;
    }
    __syncthreads();

    // R7
    {
        float v = 0.f;
        if (warp == 0) v = s_o3[lane] * s_o3[lane] + s_o3[lane + 32] * s_o3[lane + 32];
        v = wred32(v);
        if (lane == 0 && warp == 0) sc[N2O3] = v;
    }
    __syncthreads();

    // t = tanh(logmap0(proj(o3)))
    if (tid < 64) {
        float n3 = fmaxf(sqrtf(sc[N2O3]), 1e-15f);
        float p3 = (n3 > MAXN) ? MAXN / n3 : 1.f;
        float np = fmaxf(p3 * n3, 1e-15f);
        float fL = artanh_(np) / np;
        s_t[tid] = tanhf(fL * p3 * s_o3[tid]);
    }
    __syncthreads();

    // R8
    {
        float v = 0.f;
        if (warp == 0) v = s_t[lane] * s_t[lane] + s_t[lane + 32] * s_t[lane + 32];
        v = wred32(v);
        if (lane == 0 && warp == 0) sc[N2T] = v;
    }
    __syncthreads();

    // out = expmap0(t)
    if (tid < 64) {
        float nt = fmaxf(sqrtf(sc[N2T]), 1e-15f);
        float f = tanhf(nt) / nt;
        g_out[b * 64 + tid] = f * s_t[tid];
    }
}

extern "C" void kernel_launch(void* const* d_in, const int* in_sizes, int n_in,
                              void* d_out, int out_size) {
    // inputs (metadata order): self_vectors, ngh_user_vectors, ngh_entity_vectors,
    //                          item_embeddings, Wr, W_ui, lin_W, lin_b
    int B = in_sizes[0] / 64;

    dim3 gA(B, 4);
    wr_stream_kernel<<<gA, 128>>>(
        (const float*)d_in[0],  // self_vectors
        (const float*)d_in[2],  // ngh_entity_vectors
        (const float*)d_in[4]); // Wr

    kgagg_epilogue<<<B, 256>>>(
        (const float*)d_in[0],  // self_vectors
        (const float*)d_in[1],  // ngh_user_vectors
        (const float*)d_in[2],  // ngh_entity_vectors
        (const float*)d_in[3],  // item_embeddings
        (const float*)d_in[5],  // W_ui
        (const float*)d_in[6],  // lin_W
        (const float*)d_in[7],  // lin_b
        (float*)d_out);
}

// round 11
// speedup vs baseline: 1.0737x; 1.0737x over previous
#include <cuda_runtime.h>

#define FM 0xffffffffu

__device__ __forceinline__ float artanh_(float x) {
    x = fminf(fmaxf(x, -1.f + 1e-7f), 1.f - 1e-7f);
    return 0.5f * logf((1.f + x) / (1.f - x));
}

__device__ __forceinline__ float wred32(float v) {
#pragma unroll
    for (int o = 16; o; o >>= 1) v += __shfl_xor_sync(FM, v, o);
    return v;
}

__device__ __forceinline__ float gred16(float v) {
#pragma unroll
    for (int o = 8; o; o >>= 1) v += __shfl_xor_sync(FM, v, o);
    return v;
}

// Scratch for raw attention bilinear forms: E_raw[b][s] = self · Wr[b,s] · engh[b,s]
__device__ float g_Escratch[4096 * 16];

// ==================== Kernel A: pure Wr stream ====================
// grid (B, 4), 128 threads. Warp w of s-group sg handles s = sg*4 + w.
__global__ __launch_bounds__(128)
void wr_stream_kernel(const float* __restrict__ g_self,   // (B,1,64)
                      const float* __restrict__ g_engh,   // (B,1,16,64)
                      const float* __restrict__ g_Wr)     // (B,1,16,64,64)
{
    const int b    = blockIdx.x;
    const int sg   = blockIdx.y;      // 0..3
    const int tid  = threadIdx.x;
    const int lane = tid & 31;
    const int warp = tid >> 5;        // 0..3

    __shared__ float s_self[64];
    __shared__ float s_engh[4][64];

    if (tid < 64) s_self[tid] = g_self[b * 64 + tid];
#pragma unroll
    for (int i = tid; i < 256; i += 128)
        (&s_engh[0][0])[i] = g_engh[(size_t)b * 1024 + sg * 256 + i];
    __syncthreads();

    const int si  = sg * 4 + warp;
    const int l15 = lane & 15;
    const int hi  = lane >> 4;
    const float4 a = *reinterpret_cast<const float4*>(&s_self[4 * l15]);
    const float4* p = reinterpret_cast<const float4*>(g_Wr)
                    + (size_t)b * 16384 + (size_t)si * 1024 + lane;
    float acc = 0.f;
#pragma unroll 8
    for (int i = 0; i < 32; i++) {
        float4 w = __ldcs(p + i * 32);
        acc += s_engh[warp][2 * i + hi] * (w.x * a.x + w.y * a.y + w.z * a.z + w.w * a.w);
    }
    acc = wred32(acc);
    if (lane == 0) g_Escratch[b * 16 + si] = acc;
}

// ==================== Kernel B: warp-per-b epilogue ====================
// 128 threads = 4 warps; warp w handles b = blockIdx.x*4 + w.
// All reductions are warp shuffles (results broadcast in registers); per-s
// (16-wide) reductions use half-warp gred16 with 2 s per pass.
__global__ __launch_bounds__(128)
void kgagg_epilogue(const float* __restrict__ g_self,   // (B,1,64)
                    const float* __restrict__ g_ungh,   // (B,16,64)
                    const float* __restrict__ g_engh,   // (B,1,16,64)
                    const float* __restrict__ g_item,   // (B,64)
                    const float* __restrict__ g_Wui,    // (64,64)
                    const float* __restrict__ g_linW,   // (64,64)
                    const float* __restrict__ g_linb,   // (64,)
                    float* __restrict__ g_out,          // (B,1,64)
                    int B)
{
    __shared__ __align__(16) float sE[4][16][64];   // engh -> sub_e (in place)
    __shared__ __align__(16) float sU[4][16][64];   // ungh -> sub_u (in place)
    __shared__ __align__(16) float sSelf[4][64], sIv[4][64];
    __shared__ float sS[4][12][16];                 // per-s scalar arrays
    __shared__ float sV[4][2][64];                  // imW/o2 and mx buffers

    const int warp = threadIdx.x >> 5;
    const int lane = threadIdx.x & 31;
    const int b    = blockIdx.x * 4 + warp;
    if (b >= B) return;

    const int l15 = lane & 15;
    const int hi  = lane >> 4;
    const float MIN = 1e-15f;
    const float MAXN = 1.f - 0.004f;

    float (*E)[64] = sE[warp];
    float (*U)[64] = sU[warp];
    float* Sf = sSelf[warp];
    float* Iv = sIv[warp];
    float* y2e  = sS[warp][0];
    float* xye  = sS[warp][1];
    float* y2u  = sS[warp][2];
    float* xyu  = sS[warp][3];
    float* elog = sS[warp][4];   // reused as kae after softmax
    float* uelg = sS[warp][5];   // reused as kbe after softmax
    float* att  = sS[warp][6];
    float* uatt = sS[warp][7];
    float* ce   = sS[warp][8];
    float* cu   = sS[warp][9];
    float* kau  = sS[warp][10];
    float* kbu  = sS[warp][11];
    float* vbuf0 = sV[warp][0];  // imW, later o2
    float* vbuf1 = sV[warp][1];  // mx

    // ---- load per-b tensors into warp-private smem ----
    {
        const float4* e4 = reinterpret_cast<const float4*>(g_engh + (size_t)b * 1024);
        const float4* u4 = reinterpret_cast<const float4*>(g_ungh + (size_t)b * 1024);
#pragma unroll
        for (int i = lane; i < 256; i += 32) {
            reinterpret_cast<float4*>(&E[0][0])[i] = e4[i];
            reinterpret_cast<float4*>(&U[0][0])[i] = u4[i];
        }
        if (lane < 16)
            reinterpret_cast<float4*>(Sf)[lane] =
                reinterpret_cast<const float4*>(g_self + (size_t)b * 64)[lane];
        else
            reinterpret_cast<float4*>(Iv)[lane - 16] =
                reinterpret_cast<const float4*>(g_item + (size_t)b * 64)[lane - 16];
    }
    __syncwarp();

    const float self0 = Sf[lane], self1 = Sf[lane + 32];
    const float iv0   = Iv[lane], iv1   = Iv[lane + 32];

    // ---- base-point norms + logmap0 scalars (broadcast in registers) ----
    const float x2self = wred32(self0 * self0 + self1 * self1);
    const float x2iv   = wred32(iv0 * iv0 + iv1 * iv1);
    float nself = fmaxf(sqrtf(x2self), MIN);
    const float fself = artanh_(nself) / nself;
    float niv = fmaxf(sqrtf(x2iv), MIN);
    const float fiv = artanh_(niv) / niv;

    float sfr[4], ivr[4];
#pragma unroll
    for (int j = 0; j < 4; j++) { sfr[j] = Sf[l15 + 16 * j]; ivr[j] = Iv[l15 + 16 * j]; }

    // ---- per-s norms & dots (2 s per pass) ----
#pragma unroll
    for (int k = 0; k < 8; k++) {
        int s = 2 * k + hi;
        float pe = 0.f, pxe = 0.f, pu = 0.f, pxu = 0.f;
#pragma unroll
        for (int j = 0; j < 4; j++) {
            float ev = E[s][l15 + 16 * j]; pe += ev * ev; pxe += ev * sfr[j];
            float uv = U[s][l15 + 16 * j]; pu += uv * uv; pxu += uv * ivr[j];
        }
        pe = gred16(pe); pxe = gred16(pxe); pu = gred16(pu); pxu = gred16(pxu);
        if (l15 == 0) { y2e[s] = pe; xye[s] = pxe; y2u[s] = pu; xyu[s] = pxu; }
    }
    __syncwarp();

    // ---- entity logits: e[s] = fself * fe[s] * E_raw[b,s] ----
    if (lane < 16) {
        float ne = fmaxf(sqrtf(y2e[lane]), MIN);
        float fe = artanh_(ne) / ne;
        elog[lane] = fself * fe * g_Escratch[b * 16 + lane];
    }

    // ---- imW[r] = fiv * sum_d Wui[r,d]*iv[d]  (2 r per pass) ----
#pragma unroll
    for (int k = 0; k < 32; k++) {
        int r = 2 * k + hi;
        float v = 0.f;
#pragma unroll
        for (int j = 0; j < 4; j++) v += g_Wui[r * 64 + l15 + 16 * j] * ivr[j];
        v = gred16(v);
        if (l15 == 0) vbuf0[r] = fiv * v;
    }
    __syncwarp();

    // ---- u logits: ue[s] = fu[s] * dot(imW, ungh[s]) ----
    {
        float imwr[4];
#pragma unroll
        for (int j = 0; j < 4; j++) imwr[j] = vbuf0[l15 + 16 * j];
#pragma unroll
        for (int k = 0; k < 8; k++) {
            int s = 2 * k + hi;
            float p = 0.f;
#pragma unroll
            for (int j = 0; j < 4; j++) p += imwr[j] * U[s][l15 + 16 * j];
            p = gred16(p);
            if (l15 == 0) {
                float nu = fmaxf(sqrtf(y2u[s]), MIN);
                float fu = artanh_(nu) / nu;
                uelg[s] = fu * p;
            }
        }
    }
    __syncwarp();

    // ---- softmaxes over 16 (both halves mirror s = lane&15) ----
    {
        int s = lane & 15;
        float v1 = elog[s], v2 = uelg[s];
        float m1 = v1, m2 = v2;
#pragma unroll
        for (int o = 8; o; o >>= 1) {
            m1 = fmaxf(m1, __shfl_xor_sync(FM, m1, o));
            m2 = fmaxf(m2, __shfl_xor_sync(FM, m2, o));
        }
        float e1 = expf(v1 - m1), e2 = expf(v2 - m2);
        float s1 = e1, s2 = e2;
#pragma unroll
        for (int o = 8; o; o >>= 1) {
            s1 += __shfl_xor_sync(FM, s1, o);
            s2 += __shfl_xor_sync(FM, s2, o);
        }
        __syncwarp();
        if (lane < 16) { att[lane] = e1 / s1; uatt[lane] = e2 / s2; }
    }
    __syncwarp();

    // ---- mobius_add(-p, y) coefficients per s ----
    if (lane < 16) {
        int s = lane;
        float t2 = 2.f * xye[s];
        float den = fmaxf(1.f - t2 + x2self * y2e[s], MIN);
        elog[s] = -(1.f - t2 + y2e[s]) / den;   // kae
        uelg[s] = (1.f - x2self) / den;          // kbe
        float t2u = 2.f * xyu[s];
        float denu = fmaxf(1.f - t2u + x2iv * y2u[s], MIN);
        kau[s] = -(1.f - t2u + y2u[s]) / denu;
        kbu[s] = (1.f - x2iv) / denu;
    }
    __syncwarp();

    // ---- sub in place ----
#pragma unroll
    for (int s = 0; s < 16; s++) {
        float ka = elog[s], kb = uelg[s];
        E[s][lane]      = ka * self0 + kb * E[s][lane];
        E[s][lane + 32] = ka * self1 + kb * E[s][lane + 32];
        float ka2 = kau[s], kb2 = kbu[s];
        U[s][lane]      = ka2 * iv0 + kb2 * U[s][lane];
        U[s][lane + 32] = ka2 * iv1 + kb2 * U[s][lane + 32];
    }
    __syncwarp();

    // ---- sub norms -> attention-weighted logmap coefficients ----
#pragma unroll
    for (int k = 0; k < 8; k++) {
        int s = 2 * k + hi;
        float pe = 0.f, pu = 0.f;
#pragma unroll
        for (int j = 0; j < 4; j++) {
            float v = E[s][l15 + 16 * j]; pe += v * v;
            float u = U[s][l15 + 16 * j]; pu += u * u;
        }
        pe = gred16(pe); pu = gred16(pu);
        if (l15 == 0) {
            float lamE = fmaxf(2.f / (1.f - x2self), MIN);
            float sne = fmaxf(sqrtf(pe), MIN);
            ce[s] = att[s] * (2.f / lamE) * artanh_(sne) / sne;
            float lamU = fmaxf(2.f / (1.f - x2iv), MIN);
            float snu = fmaxf(sqrtf(pu), MIN);
            cu[s] = uatt[s] * (2.f / lamU) * artanh_(snu) / snu;
        }
    }
    __syncwarp();

    // ---- aggregate over s ----
    float a0 = 0.f, a1 = 0.f, b0 = 0.f, b1 = 0.f;
#pragma unroll
    for (int s = 0; s < 16; s++) {
        float c1 = ce[s], c2 = cu[s];
        a0 += c1 * E[s][lane]; a1 += c1 * E[s][lane + 32];
        b0 += c2 * U[s][lane]; b1 += c2 * U[s][lane + 32];
    }

    const float n2agge = wred32(a0 * a0 + a1 * a1);
    const float dsae   = wred32(self0 * a0 + self1 * a1);
    const float n2aggu = wred32(b0 * b0 + b1 * b1);
    const float diau   = wred32(iv0 * b0 + iv1 * b1);

    // ---- expmap at base + mobius_add(base, second) -> kg, ua ----
    float kg0, kg1, ua0, ua1;
    {
        float un  = fmaxf(sqrtf(n2agge), MIN);
        float lam = fmaxf(2.f / (1.f - x2self), MIN);
        float f   = tanhf(lam * un * 0.5f) / un;
        float xy = f * dsae, y2 = f * f * n2agge;
        float den = fmaxf(1.f + 2.f * xy + x2self * y2, MIN);
        kg0 = ((1.f + 2.f * xy + y2) * self0 + (1.f - x2self) * f * a0) / den;
        kg1 = ((1.f + 2.f * xy + y2) * self1 + (1.f - x2self) * f * a1) / den;

        float un2  = fmaxf(sqrtf(n2aggu), MIN);
        float lam2 = fmaxf(2.f / (1.f - x2iv), MIN);
        float f2   = tanhf(lam2 * un2 * 0.5f) / un2;
        float xy2 = f2 * diau, yy2 = f2 * f2 * n2aggu;
        float den2 = fmaxf(1.f + 2.f * xy2 + x2iv * yy2, MIN);
        ua0 = ((1.f + 2.f * xy2 + yy2) * iv0 + (1.f - x2iv) * f2 * b0) / den2;
        ua1 = ((1.f + 2.f * xy2 + yy2) * iv1 + (1.f - x2iv) * f2 * b1) / den2;
    }

    const float n2kg = wred32(kg0 * kg0 + kg1 * kg1);
    const float dskg = wred32(self0 * kg0 + self1 * kg1);
    const float n2ua = wred32(ua0 * ua0 + ua1 * ua1);

    // ---- o1 = mobius_add(self, kg) ----
    float o1_0, o1_1;
    {
        float den = fmaxf(1.f + 2.f * dskg + x2self * n2kg, MIN);
        o1_0 = ((1.f + 2.f * dskg + n2kg) * self0 + (1.f - x2self) * kg0) / den;
        o1_1 = ((1.f + 2.f * dskg + n2kg) * self1 + (1.f - x2self) * kg1) / den;
    }

    const float n2o1  = wred32(o1_0 * o1_0 + o1_1 * o1_1);
    const float do1ua = wred32(o1_0 * ua0 + o1_1 * ua1);

    // ---- o2 = mobius_add(o1, ua) ----
    float o2_0, o2_1;
    {
        float den = fmaxf(1.f + 2.f * do1ua + n2o1 * n2ua, MIN);
        o2_0 = ((1.f + 2.f * do1ua + n2ua) * o1_0 + (1.f - n2o1) * ua0) / den;
        o2_1 = ((1.f + 2.f * do1ua + n2ua) * o1_1 + (1.f - n2o1) * ua1) / den;
    }
    vbuf0[lane] = o2_0; vbuf0[lane + 32] = o2_1;
    __syncwarp();

    // ---- mx = lin_W @ o2 (2 r per pass) ----
    {
        float o2r[4];
#pragma unroll
        for (int j = 0; j < 4; j++) o2r[j] = vbuf0[l15 + 16 * j];
#pragma unroll
        for (int k = 0; k < 32; k++) {
            int r = 2 * k + hi;
            float v = 0.f;
#pragma unroll
            for (int j = 0; j < 4; j++) v += g_linW[r * 64 + l15 + 16 * j] * o2r[j];
            v = gred16(v);
            if (l15 == 0) vbuf1[r] = v;
        }
    }
    __syncwarp();
    const float mx0 = vbuf1[lane], mx1 = vbuf1[lane + 32];
    const float lb0 = g_linb[lane], lb1 = g_linb[lane + 32];

    const float mxn2 = wred32(mx0 * mx0 + mx1 * mx1);
    const float xn2  = wred32(o2_0 * o2_0 + o2_1 * o2_1);
    const float nb2  = wred32(lb0 * lb0 + lb1 * lb1);

    // ---- res = mobius_matvec scale; hb = expmap0(lin_b) ----
    float r0, r1, h0, h1;
    {
        float xn  = fmaxf(sqrtf(xn2), MIN);
        float mxn = fmaxf(sqrtf(mxn2), MIN);
        float f = tanhf(mxn / xn * artanh_(xn)) / mxn;
        r0 = f * mx0; r1 = f * mx1;
        float nb = fmaxf(sqrtf(nb2), MIN);
        float fb = tanhf(nb) / nb;
        h0 = fb * lb0; h1 = fb * lb1;
    }

    const float nres2 = wred32(r0 * r0 + r1 * r1);
    const float nhb2  = wred32(h0 * h0 + h1 * h1);
    const float drh   = wred32(r0 * h0 + r1 * h1);

    // ---- o3 = mobius_add(proj(res), proj(hb)) ----
    float o3_0, o3_1;
    {
        float nr = fmaxf(sqrtf(nres2), MIN);
        float pr = (nr > MAXN) ? MAXN / nr : 1.f;
        float nh = fmaxf(sqrtf(nhb2), MIN);
        float ph = (nh > MAXN) ? MAXN / nh : 1.f;
        float x2 = pr * pr * nres2;
        float y2 = ph * ph * nhb2;
        float xy = pr * ph * drh;
        float den = fmaxf(1.f + 2.f * xy + x2 * y2, MIN);
        o3_0 = ((1.f + 2.f * xy + y2) * pr * r0 + (1.f - x2) * ph * h0) / den;
        o3_1 = ((1.f + 2.f * xy + y2) * pr * r1 + (1.f - x2) * ph * h1) / den;
    }

    const float n2o3 = wred32(o3_0 * o3_0 + o3_1 * o3_1);

    // ---- t = tanh(logmap0(proj(o3))) ----
    float t0, t1;
    {
        float n3 = fmaxf(sqrtf(n2o3), MIN);
        float p3 = (n3 > MAXN) ? MAXN / n3 : 1.f;
        float np = fmaxf(p3 * n3, MIN);
        float fL = artanh_(np) / np;
        t0 = tanhf(fL * p3 * o3_0);
        t1 = tanhf(fL * p3 * o3_1);
    }

    const float n2t = wred32(t0 * t0 + t1 * t1);

    // ---- out = expmap0(t) ----
    {
        float nt = fmaxf(sqrtf(n2t), MIN);
        float f = tanhf(nt) / nt;
        g_out[(size_t)b * 64 + lane]      = f * t0;
        g_out[(size_t)b * 64 + lane + 32] = f * t1;
    }
}

extern "C" void kernel_launch(void* const* d_in, const int* in_sizes, int n_in,
                              void* d_out, int out_size) {
    // inputs (metadata order): self_vectors, ngh_user_vectors, ngh_entity_vectors,
    //                          item_embeddings, Wr, W_ui, lin_W, lin_b
    int B = in_sizes[0] / 64;

    dim3 gA(B, 4);
    wr_stream_kernel<<<gA, 128>>>(
        (const float*)d_in[0],  // self_vectors
        (const float*)d_in[2],  // ngh_entity_vectors
        (const float*)d_in[4]); // Wr

    kgagg_epilogue<<<(B + 3) / 4, 128>>>(
        (const float*)d_in[0],  // self_vectors
        (const float*)d_in[1],  // ngh_user_vectors
        (const float*)d_in[2],  // ngh_entity_vectors
        (const float*)d_in[3],  // item_embeddings
        (const float*)d_in[5],  // W_ui
        (const float*)d_in[6],  // lin_W
        (const float*)d_in[7],  // lin_b
        (float*)d_out,
        B);
}